// round 13
// baseline (speedup 1.0000x reference)
#include <cuda_runtime.h>
#include <cstdint>

// Problem constants
#define Lc     2048
#define Bc     2
#define Hc     32
#define Pc     64
#define Nc     128
#define DPROJ  4384
#define DCONVC 2304
#define DINNER 2048
#define QC     64            // chunk size
#define NCH    (Lc / QC)     // 32 chunks

// ---------------- scratch (static device globals) ---------------------------
__device__ __align__(16) float g_x  [(size_t)Bc * Hc * 4 * Lc * 32]; // (x~,x~) pairs [q4][t][32]
__device__ __align__(16) float g_xp [(size_t)Bc * Hc * Lc * 64];     // x~ plain [bh][t][64]
__device__ __align__(16) float g_gd [(size_t)Bc * Hc * 4 * Lc * 32]; // (gate,Dx) pairs [q4][t][32]
__device__ __align__(16) float g_B  [(size_t)Bc * Lc * Nc];
__device__ __align__(16) float g_C  [(size_t)Bc * Lc * Nc];
__device__ __align__(16) float g_dA [(size_t)Bc * Hc * Lc * 2];      // (dA,dA) pairs
__device__ __align__(16) float g_l  [(size_t)Bc * Hc * Lc];          // l = dt*A
__device__ __align__(16) float g_CB [(size_t)Bc * NCH * QC * QC];    // [b][c][t][i]
__device__ __align__(16) float g_stT[(size_t)Bc * Hc * NCH * Nc * Pc]; // [bh][c][n][p]

// ---------------- helpers ----------------------------------------------------
__device__ __forceinline__ uint64_t pk2(float lo, float hi) {
    uint64_t r; asm("mov.b64 %0, {%1,%2};" : "=l"(r) : "f"(lo), "f"(hi)); return r;
}
__device__ __forceinline__ void unpk2(uint64_t v, float& lo, float& hi) {
    asm("mov.b64 {%0,%1}, %2;" : "=f"(lo), "=f"(hi) : "l"(v));
}
__device__ __forceinline__ uint64_t f2fma(uint64_t a, uint64_t b, uint64_t c) {
    uint64_t d; asm("fma.rn.f32x2 %0, %1, %2, %3;" : "=l"(d) : "l"(a), "l"(b), "l"(c)); return d;
}
__device__ __forceinline__ uint64_t f2mul(uint64_t a, uint64_t b) {
    uint64_t d; asm("mul.rn.f32x2 %0, %1, %2;" : "=l"(d) : "l"(a), "l"(b)); return d;
}
__device__ __forceinline__ void cpa16(void* sm, const void* gm) {
    unsigned sa = (unsigned)__cvta_generic_to_shared(sm);
    asm volatile("cp.async.cg.shared.global [%0], [%1], 16;" :: "r"(sa), "l"(gm));
}
__device__ __forceinline__ float fast_silu(float v) {
    return v * (1.f / (1.f + __expf(-v)));
}

// ---------------- pre-pass ---------------------------------------------------
__global__ void prepass_kernel(const float* __restrict__ zx,
                               const float* __restrict__ cw,
                               const float* __restrict__ cb,
                               const float* __restrict__ dt_bias,
                               const float* __restrict__ a_log,
                               const float* __restrict__ d_param,
                               const float* __restrict__ dt_scale) {
    int bt  = blockIdx.x;            // b*L + t
    int b   = bt >> 11;
    int t   = bt & (Lc - 1);
    int idx = blockIdx.y * 256 + threadIdx.x;
    if (idx >= DCONVC + Hc) return;

    if (idx < DCONVC) {
        int cc = idx;
        int col = DINNER + cc;
        float acc = cb[cc];
        const float* w = cw + cc * 4;
        #pragma unroll
        for (int i = 0; i < 4; ++i) {
            int l2 = t - 3 + i;
            if (l2 >= 0) acc += w[i] * zx[((size_t)(b * Lc + l2)) * DPROJ + col];
        }
        float v = fast_silu(acc);
        if (cc < DINNER) {
            int h = cc >> 6, p = cc & 63;
            float draw = zx[(size_t)bt * DPROJ + (DPROJ - Hc) + h] * dt_scale[h] + dt_bias[h];
            float dt = (draw > 20.f) ? draw : log1pf(expf(draw));
            dt = fminf(fmaxf(dt, 0.f), 100.f);
            float xt = dt * v;                       // x~ = dt * x
            size_t o = ((((size_t)(b * Hc + h) * 4 + (p >> 4)) * Lc + t) * 32 + (p & 15) * 2);
            g_x[o]     = xt;
            g_x[o + 1] = xt;
            g_xp[((size_t)(b * Hc + h) * Lc + t) * 64 + p] = xt;
            float z = zx[(size_t)bt * DPROJ + cc];
            g_gd[o]     = fast_silu(z);              // gate
            g_gd[o + 1] = d_param[h] * v;            // Dh * x
        } else if (cc < DINNER + Nc) {
            g_B[((size_t)(b * Lc + t)) * Nc + (cc - DINNER)] = v;
        } else {
            g_C[((size_t)(b * Lc + t)) * Nc + (cc - DINNER - Nc)] = v;
        }
    } else {
        int h = idx - DCONVC;
        float draw = zx[(size_t)bt * DPROJ + (DPROJ - Hc) + h] * dt_scale[h] + dt_bias[h];
        float dt = (draw > 20.f) ? draw : log1pf(expf(draw));
        dt = fminf(fmaxf(dt, 0.f), 100.f);
        float A  = -expf(a_log[h]);
        float l  = dt * A;
        float dA = expf(l);
        size_t o = ((size_t)(b * Hc + h) * Lc + t) * 2;
        g_dA[o]     = dA;
        g_dA[o + 1] = dA;
        g_l[(size_t)(b * Hc + h) * Lc + t] = l;
    }
}

// ---------------- CB kernel: CB[t][i] = C_t . B_i per (b,chunk) --------------
__global__ void __launch_bounds__(256)
cb_kernel() {
    const int bc = blockIdx.x;          // b*NCH + c
    const int b  = bc >> 5;
    const int c  = bc & 31;
    const int tid = threadIdx.x;

    __shared__ float sB[QC * 132];      // B rows padded to 132 floats

    // FIX: full 128 floats (32 float4) per B row
    for (int idx = tid; idx < QC * 32; idx += 256) {
        int row = idx >> 5, sg = idx & 31;
        cpa16(&sB[row * 132 + sg * 4],
              g_B + ((size_t)b * Lc + c * QC + row) * Nc + sg * 4);
    }
    asm volatile("cp.async.commit_group;");
    asm volatile("cp.async.wait_group 0;");
    __syncthreads();

    const int t  = tid >> 2;
    const int ig = tid & 3;
    const float4* c4p = (const float4*)(g_C + ((size_t)b * Lc + c * QC + t) * Nc);
    float acc[16];
    #pragma unroll
    for (int j = 0; j < 16; ++j) acc[j] = 0.f;

    for (int nq = 0; nq < 32; ++nq) {
        float4 cv = __ldg(c4p + nq);
        #pragma unroll
        for (int j = 0; j < 16; ++j) {
            float4 bv = *(const float4*)&sB[(ig * 16 + j) * 132 + nq * 4];
            acc[j] += cv.x * bv.x + cv.y * bv.y + cv.z * bv.z + cv.w * bv.w;
        }
    }
    float* dst = g_CB + ((size_t)bc * QC + t) * QC + ig * 16;
    #pragma unroll
    for (int j = 0; j < 16; ++j) dst[j] = acc[j];
}

// ---------------- state-only scan kernel -------------------------------------
// grid 256 = (b,h,pquarter), block 128 = 4 warps; warp = 4p, lanes = 32 n-slices.
// s = dA*s + x~*B only; dumps chunk-start states transposed to g_stT.
#define NSTAGE 4
#define SSTEPS 8
#define NITER  (Lc / SSTEPS)

__global__ void __launch_bounds__(128, 2)
scan_kernel(const float* __restrict__ init_state) {
    const int bid = blockIdx.x;
    const int b   = bid >> 7;
    const int h   = (bid >> 2) & 31;
    const int pc4 = bid & 3;
    const int bh  = b * Hc + h;
    const int tid = threadIdx.x;
    const int pg  = tid >> 5;
    const int jn  = tid & 31;

    __shared__ __align__(16) float sB [NSTAGE][SSTEPS][Nc];
    __shared__ __align__(16) float sX [NSTAGE][SSTEPS][32];
    __shared__ __align__(16) float sdA[NSTAGE][SSTEPS][2];

    const int q4 = bh * 4 + pc4;
    const float4* gB  = (const float4*)(g_B + (size_t)b * Lc * Nc);
    const float4* gX  = (const float4*)(g_x + (size_t)q4 * Lc * 32);
    const float4* gdA = (const float4*)(g_dA + (size_t)bh * Lc * 2);

    auto issue_stage = [&](int k, int buf) {
        const float4* srcB = gB + (size_t)k * 256;
        cpa16(&sB[buf][0][tid * 4], srcB + tid);
        cpa16(&sB[buf][0][(tid + 128) * 4], srcB + tid + 128);
        if (tid < 64) {
            cpa16(&sX[buf][0][tid * 4], gX + (size_t)k * 64 + tid);
            if (tid < 4)
                cpa16(&sdA[buf][0][tid * 4], gdA + (size_t)k * 4 + tid);
        }
    };

    uint64_t s2[4][2];
    #pragma unroll
    for (int pp = 0; pp < 4; ++pp) {
        int p = pc4 * 16 + pg * 4 + pp;
        const float4* ist = (const float4*)(init_state +
                            ((size_t)(bh * Pc + p)) * Nc + jn * 4);
        float4 v0 = ist[0];
        s2[pp][0] = pk2(v0.x, v0.y);
        s2[pp][1] = pk2(v0.z, v0.w);
    }

    #pragma unroll
    for (int s = 0; s < NSTAGE; ++s) {
        issue_stage(s, s);
        asm volatile("cp.async.commit_group;");
    }

    for (int k = 0; k < NITER; ++k) {
        asm volatile("cp.async.wait_group %0;" :: "n"(NSTAGE - 1));
        __syncthreads();
        const int buf = k & (NSTAGE - 1);

        if ((k & 7) == 0) {
            // dump chunk-start state (transposed): g_stT[bh][c][n][p]
            int c = k >> 3;
            size_t base = (((size_t)(bh * NCH + c)) * Nc + jn * 4) * Pc
                          + pc4 * 16 + pg * 4;
            #pragma unroll
            for (int pp = 0; pp < 4; ++pp) {
                float a0, a1, a2, a3;
                unpk2(s2[pp][0], a0, a1);
                unpk2(s2[pp][1], a2, a3);
                g_stT[base + pp]          = a0;
                g_stT[base + Pc + pp]     = a1;
                g_stT[base + 2 * Pc + pp] = a2;
                g_stT[base + 3 * Pc + pp] = a3;
            }
        }

        #pragma unroll
        for (int u = 0; u < SSTEPS; ++u) {
            uint64_t dA2 = *(const uint64_t*)&sdA[buf][u][0];
            ulonglong2 xa = *(const ulonglong2*)&sX[buf][u][pg * 8];
            ulonglong2 xb = *(const ulonglong2*)&sX[buf][u][pg * 8 + 4];
            ulonglong2 bv = *(const ulonglong2*)&sB[buf][u][jn * 4];
            #pragma unroll
            for (int pp = 0; pp < 4; ++pp) {
                uint64_t xx2 = (pp == 0) ? xa.x : (pp == 1) ? xa.y : (pp == 2) ? xb.x : xb.y;
                s2[pp][0] = f2fma(dA2, s2[pp][0], f2mul(xx2, bv.x));
                s2[pp][1] = f2fma(dA2, s2[pp][1], f2mul(xx2, bv.y));
            }
        }

        __syncthreads();
        int kn = k + NSTAGE;
        if (kn < NITER) issue_stage(kn, buf);
        asm volatile("cp.async.commit_group;");
    }
}

// ---------------- Y kernel: per (b,h,chunk) GEMM -----------------------------
// Y(64x64) = M(64x192) @ D(192x64);  M = [decay.CB | E.C],  D = [Xtilde ; S^T]
#define SMEM_Y (QC * 193 * 4 + 192 * 68 * 4 + QC * 4)   // 101888 bytes

__global__ void __launch_bounds__(256, 2)
y_kernel(float* __restrict__ out) {
    extern __shared__ char dyn[];
    float* sM  = (float*)dyn;                               // [64][193]
    float* sD  = (float*)(dyn + QC * 193 * 4);              // [192][68]
    float* sac = (float*)(dyn + QC * 193 * 4 + 192 * 68 * 4); // [64]

    const int bid = blockIdx.x;
    const int c   = bid & 31;
    const int bh  = bid >> 5;
    const int b   = bh >> 5;
    const int h   = bh & 31;
    const int tid = threadIdx.x;

    // stage D: X rows (0..63), S^T rows (64..191)
    for (int idx = tid; idx < 64 * 16; idx += 256) {
        int i = idx >> 4, sg = idx & 15;
        cpa16(&sD[i * 68 + sg * 4],
              g_xp + ((size_t)bh * Lc + c * QC + i) * 64 + sg * 4);
    }
    for (int idx = tid; idx < 128 * 16; idx += 256) {
        int n = idx >> 4, sg = idx & 15;
        cpa16(&sD[(64 + n) * 68 + sg * 4],
              g_stT + (((size_t)(bh * NCH + c)) * Nc + n) * Pc + sg * 4);
    }
    asm volatile("cp.async.commit_group;");

    // ac = inclusive cumsum of l over the chunk
    if (tid < 64) {
        float v = g_l[(size_t)bh * Lc + c * QC + tid];
        #pragma unroll
        for (int off = 1; off < 32; off <<= 1) {
            float r = __shfl_up_sync(0xffffffffu, v, off);
            if ((tid & 31) >= off) v += r;
        }
        sac[tid] = v;
    }
    __syncthreads();
    if (tid >= 32 && tid < 64) sac[tid] += sac[31];
    __syncthreads();

    // build M
    {
        int t = tid >> 2, kg = tid & 3;
        float act = sac[t];
        float Et = __expf(act);
        const float* cbrow = g_CB + (((size_t)(b * NCH + c)) * QC + t) * QC;
        const float* crow  = g_C  + ((size_t)b * Lc + c * QC + t) * Nc;
        #pragma unroll 4
        for (int kk = 0; kk < 48; ++kk) {
            int k = kg * 48 + kk;
            float v;
            if (k < QC) v = (k <= t) ? __expf(act - sac[k]) * __ldg(cbrow + k) : 0.f;
            else        v = Et * __ldg(crow + (k - QC));
            sM[t * 193 + k] = v;
        }
    }
    asm volatile("cp.async.wait_group 0;");
    __syncthreads();

    // GEMM
    const int t  = tid & 63;
    const int ig = tid >> 6;
    uint64_t acc[8];
    #pragma unroll
    for (int j = 0; j < 8; ++j) acc[j] = 0;
    const float* mrow = &sM[t * 193];
    #pragma unroll 4
    for (int k = 0; k < 192; ++k) {
        float m = mrow[k];
        uint64_t m2 = pk2(m, m);
        const ulonglong2* dr = (const ulonglong2*)&sD[k * 68 + ig * 16];
        ulonglong2 d0 = dr[0], d1 = dr[1], d2 = dr[2], d3 = dr[3];
        acc[0] = f2fma(m2, d0.x, acc[0]);
        acc[1] = f2fma(m2, d0.y, acc[1]);
        acc[2] = f2fma(m2, d1.x, acc[2]);
        acc[3] = f2fma(m2, d1.y, acc[3]);
        acc[4] = f2fma(m2, d2.x, acc[4]);
        acc[5] = f2fma(m2, d2.y, acc[5]);
        acc[6] = f2fma(m2, d3.x, acc[6]);
        acc[7] = f2fma(m2, d3.y, acc[7]);
    }

    // epilogue: (y + Dh*x) * gate
    const float4* gdp = (const float4*)(g_gd + (((size_t)(bh * 4 + ig)) * Lc + c * QC + t) * 32);
    float* outp = out + ((size_t)b * Lc + c * QC + t) * DINNER + h * 64 + ig * 16;
    #pragma unroll
    for (int q = 0; q < 4; ++q) {
        float y0, y1, y2, y3;
        unpk2(acc[2 * q], y0, y1);
        unpk2(acc[2 * q + 1], y2, y3);
        float4 gd0 = __ldg(gdp + 2 * q);
        float4 gd1 = __ldg(gdp + 2 * q + 1);
        float4 o;
        o.x = (y0 + gd0.y) * gd0.x;
        o.y = (y1 + gd0.w) * gd0.z;
        o.z = (y2 + gd1.y) * gd1.x;
        o.w = (y3 + gd1.w) * gd1.z;
        *(float4*)(outp + q * 4) = o;
    }
}

// ---------------- launch -----------------------------------------------------
extern "C" void kernel_launch(void* const* d_in, const int* in_sizes, int n_in,
                              void* d_out, int out_size) {
    const float* zxbcdt     = (const float*)d_in[0];
    const float* conv_w     = (const float*)d_in[1];
    const float* conv_b     = (const float*)d_in[2];
    const float* dt_bias    = (const float*)d_in[3];
    const float* a_log      = (const float*)d_in[4];
    const float* d_param    = (const float*)d_in[5];
    const float* dt_scale   = (const float*)d_in[6];
    const float* init_state = (const float*)d_in[7];
    float* out = (float*)d_out;

    cudaFuncSetAttribute(y_kernel, cudaFuncAttributeMaxDynamicSharedMemorySize, SMEM_Y);

    dim3 pg(Bc * Lc, (DCONVC + Hc + 255) / 256);
    prepass_kernel<<<pg, 256>>>(zxbcdt, conv_w, conv_b, dt_bias, a_log, d_param, dt_scale);
    cb_kernel<<<Bc * NCH, 256>>>();
    scan_kernel<<<Bc * Hc * 4, 128>>>(init_state);
    y_kernel<<<Bc * Hc * NCH, 256, SMEM_Y>>>(out);
}

// round 14
// speedup vs baseline: 1.2339x; 1.2339x over previous
#include <cuda_runtime.h>
#include <cstdint>

// Problem constants
#define Lc     2048
#define Bc     2
#define Hc     32
#define Pc     64
#define Nc     128
#define DPROJ  4384
#define DCONVC 2304
#define DINNER 2048
#define QC     64            // chunk size
#define NCH    (Lc / QC)     // 32 chunks

// ---------------- scratch (static device globals) ---------------------------
__device__ __align__(16) float g_xp [(size_t)Bc * Hc * Lc * 64];       // x~ [bh][t][64]
__device__ __align__(16) float g_gd [(size_t)Bc * Hc * 4 * Lc * 32];   // (gate,Dx) pairs
__device__ __align__(16) float g_B  [(size_t)Bc * Lc * Nc];
__device__ __align__(16) float g_C  [(size_t)Bc * Lc * Nc];
__device__ __align__(16) float g_l  [(size_t)Bc * Hc * Lc];            // l = dt*A
__device__ __align__(16) float g_dAs[(size_t)Bc * Hc * Lc];            // dA scalar
__device__ __align__(16) float g_CB [(size_t)Bc * NCH * QC * QC];      // [b][c][t][i]
__device__ __align__(16) float g_G  [(size_t)Bc * Hc * NCH * Nc * Pc]; // [bhc][n][p]
__device__ __align__(16) float g_stT[(size_t)Bc * Hc * NCH * Nc * Pc]; // [bhc][n][p]
__device__ __align__(16) float g_E  [(size_t)Bc * Hc * NCH];           // chunk decay

// ---------------- helpers ----------------------------------------------------
__device__ __forceinline__ uint64_t pk2(float lo, float hi) {
    uint64_t r; asm("mov.b64 %0, {%1,%2};" : "=l"(r) : "f"(lo), "f"(hi)); return r;
}
__device__ __forceinline__ void unpk2(uint64_t v, float& lo, float& hi) {
    asm("mov.b64 {%0,%1}, %2;" : "=f"(lo), "=f"(hi) : "l"(v));
}
__device__ __forceinline__ uint64_t f2fma(uint64_t a, uint64_t b, uint64_t c) {
    uint64_t d; asm("fma.rn.f32x2 %0, %1, %2, %3;" : "=l"(d) : "l"(a), "l"(b), "l"(c)); return d;
}
__device__ __forceinline__ void cpa16(void* sm, const void* gm) {
    unsigned sa = (unsigned)__cvta_generic_to_shared(sm);
    asm volatile("cp.async.cg.shared.global [%0], [%1], 16;" :: "r"(sa), "l"(gm));
}
__device__ __forceinline__ float fast_silu(float v) {
    return v * (1.f / (1.f + __expf(-v)));
}

// ---------------- pre-pass ---------------------------------------------------
__global__ void prepass_kernel(const float* __restrict__ zx,
                               const float* __restrict__ cw,
                               const float* __restrict__ cb,
                               const float* __restrict__ dt_bias,
                               const float* __restrict__ a_log,
                               const float* __restrict__ d_param,
                               const float* __restrict__ dt_scale) {
    int bt  = blockIdx.x;            // b*L + t
    int b   = bt >> 11;
    int t   = bt & (Lc - 1);
    int idx = blockIdx.y * 256 + threadIdx.x;
    if (idx >= DCONVC + Hc) return;

    if (idx < DCONVC) {
        int cc = idx;
        int col = DINNER + cc;
        float acc = cb[cc];
        const float* w = cw + cc * 4;
        #pragma unroll
        for (int i = 0; i < 4; ++i) {
            int l2 = t - 3 + i;
            if (l2 >= 0) acc += w[i] * zx[((size_t)(b * Lc + l2)) * DPROJ + col];
        }
        float v = fast_silu(acc);
        if (cc < DINNER) {
            int h = cc >> 6, p = cc & 63;
            float draw = zx[(size_t)bt * DPROJ + (DPROJ - Hc) + h] * dt_scale[h] + dt_bias[h];
            float dt = (draw > 20.f) ? draw : log1pf(expf(draw));
            dt = fminf(fmaxf(dt, 0.f), 100.f);
            float xt = dt * v;                       // x~ = dt * x
            g_xp[((size_t)(b * Hc + h) * Lc + t) * 64 + p] = xt;
            float z = zx[(size_t)bt * DPROJ + cc];
            size_t o = ((((size_t)(b * Hc + h) * 4 + (p >> 4)) * Lc + t) * 32 + (p & 15) * 2);
            g_gd[o]     = fast_silu(z);              // gate
            g_gd[o + 1] = d_param[h] * v;            // Dh * x
        } else if (cc < DINNER + Nc) {
            g_B[((size_t)(b * Lc + t)) * Nc + (cc - DINNER)] = v;
        } else {
            g_C[((size_t)(b * Lc + t)) * Nc + (cc - DINNER - Nc)] = v;
        }
    } else {
        int h = idx - DCONVC;
        float draw = zx[(size_t)bt * DPROJ + (DPROJ - Hc) + h] * dt_scale[h] + dt_bias[h];
        float dt = (draw > 20.f) ? draw : log1pf(expf(draw));
        dt = fminf(fmaxf(dt, 0.f), 100.f);
        float A  = -expf(a_log[h]);
        float l  = dt * A;
        g_l  [(size_t)(b * Hc + h) * Lc + t] = l;
        g_dAs[(size_t)(b * Hc + h) * Lc + t] = expf(l);
    }
}

// ---------------- CB kernel: CB[t][i] = C_t . B_i per (b,chunk) --------------
__global__ void __launch_bounds__(256)
cb_kernel() {
    const int bc = blockIdx.x;          // b*NCH + c
    const int b  = bc >> 5;
    const int c  = bc & 31;
    const int tid = threadIdx.x;

    __shared__ float sB[QC * 132];

    for (int idx = tid; idx < QC * 32; idx += 256) {
        int row = idx >> 5, sg = idx & 31;
        cpa16(&sB[row * 132 + sg * 4],
              g_B + ((size_t)b * Lc + c * QC + row) * Nc + sg * 4);
    }
    asm volatile("cp.async.commit_group;");
    asm volatile("cp.async.wait_group 0;");
    __syncthreads();

    const int t  = tid >> 2;
    const int ig = tid & 3;
    const float4* c4p = (const float4*)(g_C + ((size_t)b * Lc + c * QC + t) * Nc);
    float acc[16];
    #pragma unroll
    for (int j = 0; j < 16; ++j) acc[j] = 0.f;

    for (int nq = 0; nq < 32; ++nq) {
        float4 cv = __ldg(c4p + nq);
        #pragma unroll
        for (int j = 0; j < 16; ++j) {
            float4 bv = *(const float4*)&sB[(ig * 16 + j) * 132 + nq * 4];
            acc[j] += cv.x * bv.x + cv.y * bv.y + cv.z * bv.z + cv.w * bv.w;
        }
    }
    float* dst = g_CB + ((size_t)bc * QC + t) * QC + ig * 16;
    #pragma unroll
    for (int j = 0; j < 16; ++j) dst[j] = acc[j];
}

// ---------------- G kernel: G_c[n][p] = sum_i w_i * x~_i[p] * B_i[n] ---------
#define SMEM_G ((64 * 64 + 64 * 128 + 64 + 64) * 4)   // 49664 B

__global__ void __launch_bounds__(256)
g_kernel() {
    extern __shared__ char dyng[];
    float* sX  = (float*)dyng;              // [i][p] 64x64
    float* sWB = sX + 64 * 64;              // [i][n] 64x128
    float* sac = sWB + 64 * 128;            // [64]
    float* sw  = sac + 64;                  // [64]

    const int bid = blockIdx.x;             // bh*NCH + c
    const int c   = bid & 31;
    const int bh  = bid >> 5;
    const int b   = bh >> 5;
    const int tid = threadIdx.x;

    const float* xbase = g_xp + ((size_t)bh * Lc + c * QC) * 64;
    for (int idx = tid; idx < 1024; idx += 256)
        cpa16(&sX[idx * 4], xbase + idx * 4);
    const float* bbase = g_B + ((size_t)b * Lc + c * QC) * Nc;
    for (int idx = tid; idx < 2048; idx += 256)
        cpa16(&sWB[idx * 4], bbase + idx * 4);
    asm volatile("cp.async.commit_group;");

    if (tid < 64) {
        float v = g_l[(size_t)bh * Lc + c * QC + tid];
        #pragma unroll
        for (int off = 1; off < 32; off <<= 1) {
            float r = __shfl_up_sync(0xffffffffu, v, off);
            if ((tid & 31) >= off) v += r;
        }
        sac[tid] = v;
    }
    __syncthreads();
    if (tid >= 32 && tid < 64) sac[tid] += sac[31];
    __syncthreads();
    float actot = sac[63];
    if (tid < 64) sw[tid] = __expf(actot - sac[tid]);
    if (tid == 0) g_E[(size_t)bh * NCH + c] = __expf(actot);
    asm volatile("cp.async.wait_group 0;");
    __syncthreads();

    // scale B rows by suffix decay w
    for (int idx = tid; idx < 2048; idx += 256) {
        int i = idx >> 5;
        float4* pp = (float4*)&sWB[idx * 4];
        float4 v = *pp;
        float w = sw[i];
        v.x *= w; v.y *= w; v.z *= w; v.w *= w;
        *pp = v;
    }
    __syncthreads();

    // GEMM: out rows = n (128), cols = p (64); tile 8n x 4p per thread
    const int n0 = (tid >> 4) * 8;
    const int p0 = (tid & 15) * 4;
    uint64_t acc[8][2];
    #pragma unroll
    for (int j = 0; j < 8; ++j) { acc[j][0] = 0; acc[j][1] = 0; }

    for (int i = 0; i < 64; ++i) {
        ulonglong2 xv = *(const ulonglong2*)&sX[i * 64 + p0];   // 4 p as 2 f2
        float wb[8];
        *(float4*)&wb[0] = *(const float4*)&sWB[i * 128 + n0];
        *(float4*)&wb[4] = *(const float4*)&sWB[i * 128 + n0 + 4];
        #pragma unroll
        for (int j = 0; j < 8; ++j) {
            uint64_t m2 = pk2(wb[j], wb[j]);
            acc[j][0] = f2fma(m2, xv.x, acc[j][0]);
            acc[j][1] = f2fma(m2, xv.y, acc[j][1]);
        }
    }
    // write G[n][p] (coalesced per n-row)
    #pragma unroll
    for (int j = 0; j < 8; ++j) {
        float* dst = g_G + (((size_t)bid) * Nc + n0 + j) * Pc + p0;
        *(ulonglong2*)dst = *(ulonglong2*)&acc[j][0];
    }
}

// ---------------- chain kernel: S <- E_c*S + G_c, dump S per chunk ----------
__global__ void __launch_bounds__(256)
chain_kernel(const float* __restrict__ init_state) {
    const int bh  = blockIdx.x;
    const int tid = threadIdx.x;
    const int n   = tid >> 1;
    const int ph  = (tid & 1) * 32;

    float S[32];
    const float* ist = init_state + (size_t)bh * Pc * Nc;
    #pragma unroll 8
    for (int j = 0; j < 32; ++j)
        S[j] = ist[(size_t)(ph + j) * Nc + n];     // [p][n] -> register [n][p-slice]

    for (int c = 0; c < NCH; ++c) {
        size_t base = (((size_t)bh * NCH + c) * Nc + n) * Pc + ph;
        #pragma unroll
        for (int j4 = 0; j4 < 8; ++j4)
            *(float4*)(g_stT + base + j4 * 4) = *(float4*)&S[j4 * 4];
        float E = g_E[(size_t)bh * NCH + c];
        #pragma unroll
        for (int j4 = 0; j4 < 8; ++j4) {
            float4 g = *(const float4*)(g_G + base + j4 * 4);
            S[j4 * 4 + 0] = E * S[j4 * 4 + 0] + g.x;
            S[j4 * 4 + 1] = E * S[j4 * 4 + 1] + g.y;
            S[j4 * 4 + 2] = E * S[j4 * 4 + 2] + g.z;
            S[j4 * 4 + 3] = E * S[j4 * 4 + 3] + g.w;
        }
    }
}

// ---------------- Y kernel ---------------------------------------------------
// Y(64x64) = M(64x192) @ D(192x64); M stored transposed sM[k][t].
#define SMEM_Y ((192 * 64 + 192 * 64 + 64 + 64) * 4)   // 98816 B

__global__ void __launch_bounds__(256, 2)
y_kernel(float* __restrict__ out) {
    extern __shared__ char dyn[];
    float* sD  = (float*)dyn;               // [192][64]
    float* sM  = sD + 192 * 64;             // [k][t]
    float* sac = sM + 192 * 64;             // [64]
    float* sdA = sac + 64;                  // [64]

    const int bid = blockIdx.x;
    const int c   = bid & 31;
    const int bh  = bid >> 5;
    const int b   = bh >> 5;
    const int h   = bh & 31;
    const int tid = threadIdx.x;

    // stage D: X rows 0..63, S^T rows 64..191 (both contiguous)
    const float* xb = g_xp + ((size_t)bh * Lc + c * QC) * 64;
    for (int idx = tid; idx < 1024; idx += 256)
        cpa16(&sD[idx * 4], xb + idx * 4);
    const float* stb = g_stT + ((size_t)bh * NCH + c) * Nc * Pc;
    for (int idx = tid; idx < 2048; idx += 256)
        cpa16(&sD[64 * 64 + idx * 4], stb + idx * 4);
    asm volatile("cp.async.commit_group;");

    if (tid < 64) {
        sdA[tid] = g_dAs[(size_t)bh * Lc + c * QC + tid];
        float v = g_l[(size_t)bh * Lc + c * QC + tid];
        #pragma unroll
        for (int off = 1; off < 32; off <<= 1) {
            float r = __shfl_up_sync(0xffffffffu, v, off);
            if ((tid & 31) >= off) v += r;
        }
        sac[tid] = v;
    }
    __syncthreads();
    if (tid >= 32 && tid < 64) sac[tid] += sac[31];
    __syncthreads();

    // build M transposed: sM[i][t] = decay(t,i)*CB[t][i]; sM[64+n][t] = E_t*C[t][n]
    if (tid < 64) {
        int t = tid;
        float Et = __expf(sac[t]);
        const float* crow = g_C + ((size_t)b * Lc + c * QC + t) * Nc;
        for (int nn = 0; nn < Nc; ++nn)
            sM[(64 + nn) * 64 + t] = Et * __ldg(crow + nn);
        const float* cbrow = g_CB + (((size_t)b * NCH + c) * QC + t) * QC;
        float w = 1.f;
        sM[t * 64 + t] = __ldg(cbrow + t);
        for (int i = t - 1; i >= 0; --i) {
            w *= sdA[i + 1];
            sM[i * 64 + t] = w * __ldg(cbrow + i);
        }
        for (int i = t + 1; i < QC; ++i) sM[i * 64 + t] = 0.f;
    }
    asm volatile("cp.async.wait_group 0;");
    __syncthreads();

    // GEMM: tile 4t x 4c per thread
    const int t0 = (tid >> 4) * 4;
    const int c0 = (tid & 15) * 4;
    uint64_t acc[4][2];
    #pragma unroll
    for (int j = 0; j < 4; ++j) { acc[j][0] = 0; acc[j][1] = 0; }

    for (int k = 0; k < 192; ++k) {
        float mv[4];
        *(float4*)mv = *(const float4*)&sM[k * 64 + t0];
        ulonglong2 dv = *(const ulonglong2*)&sD[k * 64 + c0];
        #pragma unroll
        for (int tt = 0; tt < 4; ++tt) {
            uint64_t m2 = pk2(mv[tt], mv[tt]);
            acc[tt][0] = f2fma(m2, dv.x, acc[tt][0]);
            acc[tt][1] = f2fma(m2, dv.y, acc[tt][1]);
        }
    }

    // epilogue: (y + Dh*x) * gate
    const int q4 = c0 >> 4;
    #pragma unroll
    for (int tt = 0; tt < 4; ++tt) {
        int tg = c * QC + t0 + tt;
        const float4* gdp = (const float4*)(g_gd +
            (((size_t)(bh * 4 + q4)) * Lc + tg) * 32 + (c0 & 15) * 2);
        float4 gd0 = __ldg(gdp);
        float4 gd1 = __ldg(gdp + 1);
        float y0, y1, y2, y3;
        unpk2(acc[tt][0], y0, y1);
        unpk2(acc[tt][1], y2, y3);
        float4 o;
        o.x = (y0 + gd0.y) * gd0.x;
        o.y = (y1 + gd0.w) * gd0.z;
        o.z = (y2 + gd1.y) * gd1.x;
        o.w = (y3 + gd1.w) * gd1.z;
        *(float4*)(out + ((size_t)b * Lc + tg) * DINNER + h * 64 + c0) = o;
    }
}

// ---------------- launch -----------------------------------------------------
extern "C" void kernel_launch(void* const* d_in, const int* in_sizes, int n_in,
                              void* d_out, int out_size) {
    const float* zxbcdt     = (const float*)d_in[0];
    const float* conv_w     = (const float*)d_in[1];
    const float* conv_b     = (const float*)d_in[2];
    const float* dt_bias    = (const float*)d_in[3];
    const float* a_log      = (const float*)d_in[4];
    const float* d_param    = (const float*)d_in[5];
    const float* dt_scale   = (const float*)d_in[6];
    const float* init_state = (const float*)d_in[7];
    float* out = (float*)d_out;

    cudaFuncSetAttribute(g_kernel, cudaFuncAttributeMaxDynamicSharedMemorySize, SMEM_G);
    cudaFuncSetAttribute(y_kernel, cudaFuncAttributeMaxDynamicSharedMemorySize, SMEM_Y);

    dim3 pg(Bc * Lc, (DCONVC + Hc + 255) / 256);
    prepass_kernel<<<pg, 256>>>(zxbcdt, conv_w, conv_b, dt_bias, a_log, d_param, dt_scale);
    cb_kernel<<<Bc * NCH, 256>>>();
    g_kernel<<<Bc * Hc * NCH, 256, SMEM_G>>>();
    chain_kernel<<<Bc * Hc, 256>>>(init_state);
    y_kernel<<<Bc * Hc * NCH, 256, SMEM_Y>>>(out);
}